// round 13
// baseline (speedup 1.0000x reference)
#include <cuda_runtime.h>
#include <cuda_bf16.h>

// Problem constants
#define B_      8
#define S_      4096
#define D_      1024
#define D4_     (D_ / 4)
#define G_      64
#define HSEQ_   2048
#define NCHUNK_ 32
#define CROWS_  (HSEQ_ / NCHUNK_)   // 64 rows per chunk
#define PCHUNK_ 8                   // k_pred D-split
#define PDIM_   (D_ / PCHUNK_)      // 128 d per pred block
#define RPB_    16                  // rows per copy block (deep per-thread MLP)

// Scratch (allocation-free rule: __device__ globals)
__device__ float4 g_qpartial[B_ * NCHUNK_ * D4_];   // [b][chunk][d4]
__device__ float4 g_qprobe[B_ * D4_];               // [b][d4]
__device__ float  g_logits[2 * B_ * G_];            // [t][b][g]
__device__ float  g_sse[2 * B_ * PCHUNK_];          // [t][b][chunk] SSE partials

// Side stream + events for fork-join capture (created at static init).
static cudaStream_t g_side = nullptr;
static cudaEvent_t  g_evFork = nullptr, g_evJoin = nullptr;
namespace {
struct StreamInit {
    StreamInit() {
        cudaStreamCreateWithFlags(&g_side, cudaStreamNonBlocking);
        cudaEventCreateWithFlags(&g_evFork, cudaEventDisableTiming);
        cudaEventCreateWithFlags(&g_evJoin, cudaEventDisableTiming);
    }
};
static StreamInit g_streamInit;
}

// ---------------------------------------------------------------------------
// K1: partial column sums of h (float4, streaming). grid (NCHUNK_, B_), block 256
// ---------------------------------------------------------------------------
__global__ void k_probe_partial(const float4* __restrict__ h4) {
    const int v = threadIdx.x;
    const int c = blockIdx.x;
    const int b = blockIdx.y;
    const float4* p = h4 + ((size_t)b * HSEQ_ + (size_t)c * CROWS_) * D4_ + v;
    float4 acc = make_float4(0.f, 0.f, 0.f, 0.f);
#pragma unroll 16
    for (int s = 0; s < CROWS_; ++s) {
        const float4 x = __ldcs(&p[(size_t)s * D4_]);
        acc.x += x.x; acc.y += x.y; acc.z += x.z; acc.w += x.w;
    }
    g_qpartial[(b * NCHUNK_ + c) * D4_ + v] = acc;
}

// ---------------------------------------------------------------------------
// K2: reduce partials -> q_probe (mean). grid B_, block 256
// ---------------------------------------------------------------------------
__global__ void k_qreduce() {
    const int v = threadIdx.x;
    const int b = blockIdx.x;
    float4 acc = make_float4(0.f, 0.f, 0.f, 0.f);
#pragma unroll
    for (int c = 0; c < NCHUNK_; ++c) {
        const float4 x = g_qpartial[(b * NCHUNK_ + c) * D4_ + v];
        acc.x += x.x; acc.y += x.y; acc.z += x.z; acc.w += x.w;
    }
    const float inv = 1.0f / (float)HSEQ_;
    acc.x *= inv; acc.y *= inv; acc.z *= inv; acc.w *= inv;
    g_qprobe[b * D4_ + v] = acc;
}

// ---------------------------------------------------------------------------
// K3: logits. grid (G_, B_, 2), block 256 — one 1024-dot per block.
// ---------------------------------------------------------------------------
__global__ void k_logits(const float* __restrict__ K_curr,
                         const float* __restrict__ V_curr,
                         const int*   __restrict__ active_idx) {
    const int g = blockIdx.x;
    const int b = blockIdx.y;
    const int t = blockIdx.z;
    const int tid = threadIdx.x;
    const int wid = tid >> 5, lid = tid & 31;

    const float* X = (t == 0) ? K_curr : V_curr;
    const int row = __ldg(&active_idx[b * G_ + g]);
    const float4* xr = reinterpret_cast<const float4*>(X + ((size_t)b * S_ + row) * D_);

    const float4 q = g_qprobe[b * D4_ + tid];
    const float4 x = xr[tid];
    float acc = q.x * x.x + q.y * x.y + q.z * x.z + q.w * x.w;
#pragma unroll
    for (int off = 16; off > 0; off >>= 1)
        acc += __shfl_xor_sync(0xFFFFFFFFu, acc, off);

    __shared__ float sred[8];
    if (lid == 0) sred[wid] = acc;
    __syncthreads();
    if (tid == 0) {
        float tot = 0.f;
#pragma unroll
        for (int w = 0; w < 8; ++w) tot += sred[w];
        g_logits[(t * B_ + b) * G_ + g] = tot * (1.0f / 32.0f);  // * D^-0.5
    }
}

// ---------------------------------------------------------------------------
// K4: softmax + pred + SSE partials. grid (PCHUNK_, B_, 2), block 128
// ---------------------------------------------------------------------------
__global__ void k_pred(const float* __restrict__ K_curr,
                       const float* __restrict__ V_curr,
                       const int*   __restrict__ active_idx) {
    const int chunk = blockIdx.x;
    const int b = blockIdx.y;
    const int t = blockIdx.z;
    const int tid = threadIdx.x;
    const int wid = tid >> 5, lid = tid & 31;

    __shared__ float sattn[G_];
    __shared__ int   sidx[G_];
    __shared__ float sred[4];

    if (tid < G_) sidx[tid] = active_idx[b * G_ + tid];
    if (wid == 0) {
        float v0 = g_logits[(t * B_ + b) * G_ + lid];
        float v1 = g_logits[(t * B_ + b) * G_ + lid + 32];
        float m = fmaxf(v0, v1);
#pragma unroll
        for (int off = 16; off > 0; off >>= 1)
            m = fmaxf(m, __shfl_xor_sync(0xFFFFFFFFu, m, off));
        float e0 = __expf(v0 - m), e1 = __expf(v1 - m);
        float s = e0 + e1;
#pragma unroll
        for (int off = 16; off > 0; off >>= 1)
            s += __shfl_xor_sync(0xFFFFFFFFu, s, off);
        const float inv = 1.0f / s;
        sattn[lid]      = e0 * inv;
        sattn[lid + 32] = e1 * inv;
    }
    __syncthreads();

    const float* X  = (t == 0) ? K_curr : V_curr;
    const float* Xb = X + (size_t)b * S_ * D_;
    const int d = chunk * PDIM_ + tid;

    float pred = 0.f;
#pragma unroll 16
    for (int g = 0; g < G_; ++g)
        pred = fmaf(sattn[g], __ldg(&Xb[(size_t)sidx[g] * D_ + d]), pred);

    const float4 q4 = g_qprobe[b * D4_ + (d >> 2)];
    const float qv = (d & 3) == 0 ? q4.x : (d & 3) == 1 ? q4.y : (d & 3) == 2 ? q4.z : q4.w;
    const float diff = pred - qv;
    float acc = diff * diff;

#pragma unroll
    for (int off = 16; off > 0; off >>= 1)
        acc += __shfl_xor_sync(0xFFFFFFFFu, acc, off);
    if (lid == 0) sred[wid] = acc;
    __syncthreads();
    if (tid == 0) {
        float tot = sred[0] + sred[1] + sred[2] + sred[3];
        g_sse[(t * B_ + b) * PCHUNK_ + chunk] = tot;
    }
}

// ---------------------------------------------------------------------------
// K5: blend active rows + fused gates + momentum. grid (G_, B_), block 256.
//     Writes ONLY active output rows — runs concurrently with k_copy.
// ---------------------------------------------------------------------------
__device__ __forceinline__ float sigmoidf_(float x) { return 1.0f / (1.0f + __expf(-x)); }

__global__ void k_blend(const float* __restrict__ K_curr,
                        const float* __restrict__ V_curr,
                        const float* __restrict__ K_prev,
                        const float* __restrict__ V_prev,
                        const int*   __restrict__ active_idx,
                        const float* __restrict__ momentum,
                        const float* __restrict__ Wk,
                        const float* __restrict__ bk,
                        const float* __restrict__ Wv,
                        const float* __restrict__ bv,
                        const float* __restrict__ logit_eta,
                        const float* __restrict__ alpha_logit,
                        float* __restrict__ outK,
                        float* __restrict__ outV,
                        float* __restrict__ outM) {
    const int g = blockIdx.x;
    const int b = blockIdx.y;
    const int t = threadIdx.x;

    __shared__ float s_kg, s_vg;
    __shared__ int   s_row;
    if (t == 0) {
        float ks = 0.f, vs = 0.f;
#pragma unroll
        for (int c = 0; c < PCHUNK_; ++c) {
            ks += g_sse[(0 * B_ + b) * PCHUNK_ + c];
            vs += g_sse[(1 * B_ + b) * PCHUNK_ + c];
        }
        ks *= (1.0f / (float)D_);
        vs *= (1.0f / (float)D_);
        const float alpha = sigmoidf_(alpha_logit[0]);
        const float eta   = sigmoidf_(logit_eta[0]);
        const float combined = alpha * ks + (1.0f - alpha) * vs;
        const float mnew = eta * momentum[b] + (1.0f - eta) * combined;
        if (g == 0) outM[b] = mnew;
        s_kg = sigmoidf_(ks * Wk[g * 2 + 0] + mnew * Wk[g * 2 + 1] + bk[g]);
        s_vg = sigmoidf_(vs * Wv[g * 2 + 0] + mnew * Wv[g * 2 + 1] + bv[g]);
        s_row = active_idx[b * G_ + g];
    }
    __syncthreads();

    const float kg = s_kg, vg = s_vg;
    const size_t base = ((size_t)b * S_ + s_row) * D_;

    const float4 kc = reinterpret_cast<const float4*>(K_curr + base)[t];
    const float4 kp = reinterpret_cast<const float4*>(K_prev + base)[t];
    const float4 vc = reinterpret_cast<const float4*>(V_curr + base)[t];
    const float4 vp = reinterpret_cast<const float4*>(V_prev + base)[t];

    float4 ok, ov;
    ok.x = kg * kc.x + (1.0f - kg) * kp.x;
    ok.y = kg * kc.y + (1.0f - kg) * kp.y;
    ok.z = kg * kc.z + (1.0f - kg) * kp.z;
    ok.w = kg * kc.w + (1.0f - kg) * kp.w;
    ov.x = vg * vc.x + (1.0f - vg) * vp.x;
    ov.y = vg * vc.y + (1.0f - vg) * vp.y;
    ov.z = vg * vc.z + (1.0f - vg) * vp.z;
    ov.w = vg * vc.w + (1.0f - vg) * vp.w;

    reinterpret_cast<float4*>(outK + base)[t] = ok;
    reinterpret_cast<float4*>(outV + base)[t] = ov;
}

// ---------------------------------------------------------------------------
// K6: bulk copy of all rows, skipping active rows (blend writes those).
//     grid: 2 * B_*S_ / RPB_ blocks (K/V interleaved), block 256.
//     16 front-batched float4 loads per thread (256B in flight), per-warp
//     16-bit ballot mask, no smem, no barrier.
// ---------------------------------------------------------------------------
__global__ void k_copy(const float4* __restrict__ K_curr,
                       const float4* __restrict__ V_curr,
                       const int*    __restrict__ active_idx,
                       float4* __restrict__ outK,
                       float4* __restrict__ outV) {
    const int blk    = blockIdx.x;
    const int tensor = blk & 1;                   // interleave K/V
    const int rblk   = blk >> 1;
    const int r0     = rblk * RPB_;               // row within tensor (0..32767)
    const int b      = r0 >> 12;                  // S_ = 4096
    const int s0     = r0 & (S_ - 1);
    const int tid    = threadIdx.x;
    const int lid    = tid & 31;

    const float4* src = (tensor == 0) ? K_curr : V_curr;
    float4*       dst = (tensor == 0) ? outK   : outV;
    const size_t base = ((size_t)b * S_ + s0) * D4_ + tid;

    // Front-batch all loads (active rows loaded but not stored)
    float4 v[RPB_];
#pragma unroll
    for (int i = 0; i < RPB_; ++i)
        v[i] = __ldcs(&src[base + (size_t)i * D4_]);

    // Per-warp active-row mask (broadcast L1-hit loads, no barrier)
    unsigned m = 0;
    {
        const int v0 = __ldg(&active_idx[b * G_ + lid]);
        const int v1 = __ldg(&active_idx[b * G_ + lid + 32]);
        const unsigned r0u = (unsigned)(v0 - s0);
        const unsigned r1u = (unsigned)(v1 - s0);
        if (r0u < (unsigned)RPB_) m |= 1u << r0u;
        if (r1u < (unsigned)RPB_) m |= 1u << r1u;
        m = __reduce_or_sync(0xFFFFFFFFu, m);
    }

#pragma unroll
    for (int i = 0; i < RPB_; ++i)
        if (!((m >> i) & 1u))
            __stcs(&dst[base + (size_t)i * D4_], v[i]);
}

// ---------------------------------------------------------------------------
extern "C" void kernel_launch(void* const* d_in, const int* in_sizes, int n_in,
                              void* d_out, int out_size) {
    const float* K_curr      = (const float*)d_in[0];
    const float* V_curr      = (const float*)d_in[1];
    const float* K_prev      = (const float*)d_in[2];
    const float* V_prev      = (const float*)d_in[3];
    const float* h           = (const float*)d_in[4];
    const float* momentum    = (const float*)d_in[5];
    const int*   active_idx  = (const int*)  d_in[6];
    const float* Wk          = (const float*)d_in[7];
    const float* bk          = (const float*)d_in[8];
    const float* Wv          = (const float*)d_in[9];
    const float* bv          = (const float*)d_in[10];
    const float* logit_eta   = (const float*)d_in[11];
    const float* alpha_logit = (const float*)d_in[12];

    float* out  = (float*)d_out;
    const size_t tensor_elems = (size_t)B_ * S_ * D_;
    float* outK = out;
    float* outV = out + tensor_elems;
    float* outM = out + 2 * tensor_elems;

    const bool forked = (g_side != nullptr && g_evFork != nullptr && g_evJoin != nullptr);
    cudaStream_t chain = forked ? g_side : (cudaStream_t)0;

    // ── Fork ──
    if (forked) {
        cudaEventRecord(g_evFork, 0);
        cudaStreamWaitEvent(g_side, g_evFork, 0);
    }

    // ── Main stream FIRST: bulk copy of all inactive rows (the critical path) ──
    k_copy<<<2 * B_ * S_ / RPB_, 256>>>((const float4*)K_curr, (const float4*)V_curr,
                                        active_idx, (float4*)outK, (float4*)outV);

    // ── Side stream: probe chain + blend (blend writes ONLY active rows,
    //    so it has no dependency on the bulk copy) ──
    k_probe_partial<<<dim3(NCHUNK_, B_), 256, 0, chain>>>((const float4*)h);
    k_qreduce<<<B_, 256, 0, chain>>>();
    k_logits<<<dim3(G_, B_, 2), 256, 0, chain>>>(K_curr, V_curr, active_idx);
    k_pred<<<dim3(PCHUNK_, B_, 2), PDIM_, 0, chain>>>(K_curr, V_curr, active_idx);
    k_blend<<<dim3(G_, B_), 256, 0, chain>>>(K_curr, V_curr, K_prev, V_prev, active_idx,
                                             momentum, Wk, bk, Wv, bv,
                                             logit_eta, alpha_logit,
                                             outK, outV, outM);
    if (forked) {
        cudaEventRecord(g_evJoin, g_side);
        cudaStreamWaitEvent((cudaStream_t)0, g_evJoin, 0);
    }
}

// round 14
// speedup vs baseline: 1.0559x; 1.0559x over previous
#include <cuda_runtime.h>
#include <cuda_bf16.h>

// Problem constants
#define B_      8
#define S_      4096
#define D_      1024
#define D4_     (D_ / 4)
#define G_      64
#define HSEQ_   2048
#define NCHUNK_ 32
#define CROWS_  (HSEQ_ / NCHUNK_)   // 64 rows per chunk
#define PCHUNK_ 8                   // k_pred D-split
#define PDIM_   (D_ / PCHUNK_)      // 128 d per pred block
#define RPB_    16                  // rows per copy block (deep per-thread MLP)

// Scratch (allocation-free rule: __device__ globals)
__device__ float4 g_qpartial[B_ * NCHUNK_ * D4_];   // [b][chunk][d4]
__device__ float4 g_qprobe[B_ * D4_];               // [b][d4]
__device__ float  g_logits[2 * B_ * G_];            // [t][b][g]
__device__ float  g_sse[2 * B_ * PCHUNK_];          // [t][b][chunk] SSE partials

// Side stream + events for fork-join capture (created at static init).
static cudaStream_t g_side = nullptr;
static cudaEvent_t  g_evFork = nullptr, g_evJoin = nullptr;
namespace {
struct StreamInit {
    StreamInit() {
        cudaStreamCreateWithFlags(&g_side, cudaStreamNonBlocking);
        cudaEventCreateWithFlags(&g_evFork, cudaEventDisableTiming);
        cudaEventCreateWithFlags(&g_evJoin, cudaEventDisableTiming);
    }
};
static StreamInit g_streamInit;
}

// ---------------------------------------------------------------------------
// K1: partial column sums of h (float4, streaming). grid (NCHUNK_, B_), block 256
// ---------------------------------------------------------------------------
__global__ void k_probe_partial(const float4* __restrict__ h4) {
    const int v = threadIdx.x;
    const int c = blockIdx.x;
    const int b = blockIdx.y;
    const float4* p = h4 + ((size_t)b * HSEQ_ + (size_t)c * CROWS_) * D4_ + v;
    float4 acc = make_float4(0.f, 0.f, 0.f, 0.f);
#pragma unroll 16
    for (int s = 0; s < CROWS_; ++s) {
        const float4 x = __ldcs(&p[(size_t)s * D4_]);
        acc.x += x.x; acc.y += x.y; acc.z += x.z; acc.w += x.w;
    }
    g_qpartial[(b * NCHUNK_ + c) * D4_ + v] = acc;
}

// ---------------------------------------------------------------------------
// K2: reduce partials -> q_probe (mean). grid B_, block 256
// ---------------------------------------------------------------------------
__global__ void k_qreduce() {
    const int v = threadIdx.x;
    const int b = blockIdx.x;
    float4 acc = make_float4(0.f, 0.f, 0.f, 0.f);
#pragma unroll
    for (int c = 0; c < NCHUNK_; ++c) {
        const float4 x = g_qpartial[(b * NCHUNK_ + c) * D4_ + v];
        acc.x += x.x; acc.y += x.y; acc.z += x.z; acc.w += x.w;
    }
    const float inv = 1.0f / (float)HSEQ_;
    acc.x *= inv; acc.y *= inv; acc.z *= inv; acc.w *= inv;
    g_qprobe[b * D4_ + v] = acc;
}

// ---------------------------------------------------------------------------
// K3: logits. grid (G_, B_, 2), block 256 — one 1024-dot per block.
// ---------------------------------------------------------------------------
__global__ void k_logits(const float* __restrict__ K_curr,
                         const float* __restrict__ V_curr,
                         const int*   __restrict__ active_idx) {
    const int g = blockIdx.x;
    const int b = blockIdx.y;
    const int t = blockIdx.z;
    const int tid = threadIdx.x;
    const int wid = tid >> 5, lid = tid & 31;

    const float* X = (t == 0) ? K_curr : V_curr;
    const int row = __ldg(&active_idx[b * G_ + g]);
    const float4* xr = reinterpret_cast<const float4*>(X + ((size_t)b * S_ + row) * D_);

    const float4 q = g_qprobe[b * D4_ + tid];
    const float4 x = xr[tid];
    float acc = q.x * x.x + q.y * x.y + q.z * x.z + q.w * x.w;
#pragma unroll
    for (int off = 16; off > 0; off >>= 1)
        acc += __shfl_xor_sync(0xFFFFFFFFu, acc, off);

    __shared__ float sred[8];
    if (lid == 0) sred[wid] = acc;
    __syncthreads();
    if (tid == 0) {
        float tot = 0.f;
#pragma unroll
        for (int w = 0; w < 8; ++w) tot += sred[w];
        g_logits[(t * B_ + b) * G_ + g] = tot * (1.0f / 32.0f);  // * D^-0.5
    }
}

// ---------------------------------------------------------------------------
// K4: softmax + pred + SSE partials. grid (PCHUNK_, B_, 2), block 128
// ---------------------------------------------------------------------------
__global__ void k_pred(const float* __restrict__ K_curr,
                       const float* __restrict__ V_curr,
                       const int*   __restrict__ active_idx) {
    const int chunk = blockIdx.x;
    const int b = blockIdx.y;
    const int t = blockIdx.z;
    const int tid = threadIdx.x;
    const int wid = tid >> 5, lid = tid & 31;

    __shared__ float sattn[G_];
    __shared__ int   sidx[G_];
    __shared__ float sred[4];

    if (tid < G_) sidx[tid] = active_idx[b * G_ + tid];
    if (wid == 0) {
        float v0 = g_logits[(t * B_ + b) * G_ + lid];
        float v1 = g_logits[(t * B_ + b) * G_ + lid + 32];
        float m = fmaxf(v0, v1);
#pragma unroll
        for (int off = 16; off > 0; off >>= 1)
            m = fmaxf(m, __shfl_xor_sync(0xFFFFFFFFu, m, off));
        float e0 = __expf(v0 - m), e1 = __expf(v1 - m);
        float s = e0 + e1;
#pragma unroll
        for (int off = 16; off > 0; off >>= 1)
            s += __shfl_xor_sync(0xFFFFFFFFu, s, off);
        const float inv = 1.0f / s;
        sattn[lid]      = e0 * inv;
        sattn[lid + 32] = e1 * inv;
    }
    __syncthreads();

    const float* X  = (t == 0) ? K_curr : V_curr;
    const float* Xb = X + (size_t)b * S_ * D_;
    const int d = chunk * PDIM_ + tid;

    float pred = 0.f;
#pragma unroll 16
    for (int g = 0; g < G_; ++g)
        pred = fmaf(sattn[g], __ldg(&Xb[(size_t)sidx[g] * D_ + d]), pred);

    const float4 q4 = g_qprobe[b * D4_ + (d >> 2)];
    const float qv = (d & 3) == 0 ? q4.x : (d & 3) == 1 ? q4.y : (d & 3) == 2 ? q4.z : q4.w;
    const float diff = pred - qv;
    float acc = diff * diff;

#pragma unroll
    for (int off = 16; off > 0; off >>= 1)
        acc += __shfl_xor_sync(0xFFFFFFFFu, acc, off);
    if (lid == 0) sred[wid] = acc;
    __syncthreads();
    if (tid == 0) {
        float tot = sred[0] + sred[1] + sred[2] + sred[3];
        g_sse[(t * B_ + b) * PCHUNK_ + chunk] = tot;
    }
}

// ---------------------------------------------------------------------------
// K5: blend active rows + fused gates + momentum. grid (G_, B_), block 256.
//     Writes ONLY active output rows — runs concurrently with k_copy.
// ---------------------------------------------------------------------------
__device__ __forceinline__ float sigmoidf_(float x) { return 1.0f / (1.0f + __expf(-x)); }

__global__ void k_blend(const float* __restrict__ K_curr,
                        const float* __restrict__ V_curr,
                        const float* __restrict__ K_prev,
                        const float* __restrict__ V_prev,
                        const int*   __restrict__ active_idx,
                        const float* __restrict__ momentum,
                        const float* __restrict__ Wk,
                        const float* __restrict__ bk,
                        const float* __restrict__ Wv,
                        const float* __restrict__ bv,
                        const float* __restrict__ logit_eta,
                        const float* __restrict__ alpha_logit,
                        float* __restrict__ outK,
                        float* __restrict__ outV,
                        float* __restrict__ outM) {
    const int g = blockIdx.x;
    const int b = blockIdx.y;
    const int t = threadIdx.x;

    __shared__ float s_kg, s_vg;
    __shared__ int   s_row;
    if (t == 0) {
        float ks = 0.f, vs = 0.f;
#pragma unroll
        for (int c = 0; c < PCHUNK_; ++c) {
            ks += g_sse[(0 * B_ + b) * PCHUNK_ + c];
            vs += g_sse[(1 * B_ + b) * PCHUNK_ + c];
        }
        ks *= (1.0f / (float)D_);
        vs *= (1.0f / (float)D_);
        const float alpha = sigmoidf_(alpha_logit[0]);
        const float eta   = sigmoidf_(logit_eta[0]);
        const float combined = alpha * ks + (1.0f - alpha) * vs;
        const float mnew = eta * momentum[b] + (1.0f - eta) * combined;
        if (g == 0) outM[b] = mnew;
        s_kg = sigmoidf_(ks * Wk[g * 2 + 0] + mnew * Wk[g * 2 + 1] + bk[g]);
        s_vg = sigmoidf_(vs * Wv[g * 2 + 0] + mnew * Wv[g * 2 + 1] + bv[g]);
        s_row = active_idx[b * G_ + g];
    }
    __syncthreads();

    const float kg = s_kg, vg = s_vg;
    const size_t base = ((size_t)b * S_ + s_row) * D_;

    const float4 kc = reinterpret_cast<const float4*>(K_curr + base)[t];
    const float4 kp = reinterpret_cast<const float4*>(K_prev + base)[t];
    const float4 vc = reinterpret_cast<const float4*>(V_curr + base)[t];
    const float4 vp = reinterpret_cast<const float4*>(V_prev + base)[t];

    float4 ok, ov;
    ok.x = kg * kc.x + (1.0f - kg) * kp.x;
    ok.y = kg * kc.y + (1.0f - kg) * kp.y;
    ok.z = kg * kc.z + (1.0f - kg) * kp.z;
    ok.w = kg * kc.w + (1.0f - kg) * kp.w;
    ov.x = vg * vc.x + (1.0f - vg) * vp.x;
    ov.y = vg * vc.y + (1.0f - vg) * vp.y;
    ov.z = vg * vc.z + (1.0f - vg) * vp.z;
    ov.w = vg * vc.w + (1.0f - vg) * vp.w;

    reinterpret_cast<float4*>(outK + base)[t] = ok;
    reinterpret_cast<float4*>(outV + base)[t] = ov;
}

// ---------------------------------------------------------------------------
// K6: bulk copy of all rows, skipping active rows (blend writes those).
//     grid: 2 * B_*S_ / RPB_ blocks (K/V interleaved), block 256.
//     16 front-batched float4 loads per thread (256B in flight), per-warp
//     16-bit ballot mask, no smem, no barrier.
// ---------------------------------------------------------------------------
__global__ void k_copy(const float4* __restrict__ K_curr,
                       const float4* __restrict__ V_curr,
                       const int*    __restrict__ active_idx,
                       float4* __restrict__ outK,
                       float4* __restrict__ outV) {
    const int blk    = blockIdx.x;
    const int tensor = blk & 1;                   // interleave K/V
    const int rblk   = blk >> 1;
    const int r0     = rblk * RPB_;               // row within tensor (0..32767)
    const int b      = r0 >> 12;                  // S_ = 4096
    const int s0     = r0 & (S_ - 1);
    const int tid    = threadIdx.x;
    const int lid    = tid & 31;

    const float4* src = (tensor == 0) ? K_curr : V_curr;
    float4*       dst = (tensor == 0) ? outK   : outV;
    const size_t base = ((size_t)b * S_ + s0) * D4_ + tid;

    // Front-batch all loads (active rows loaded but not stored)
    float4 v[RPB_];
#pragma unroll
    for (int i = 0; i < RPB_; ++i)
        v[i] = __ldcs(&src[base + (size_t)i * D4_]);

    // Per-warp active-row mask (broadcast L1-hit loads, no barrier)
    unsigned m = 0;
    {
        const int v0 = __ldg(&active_idx[b * G_ + lid]);
        const int v1 = __ldg(&active_idx[b * G_ + lid + 32]);
        const unsigned r0u = (unsigned)(v0 - s0);
        const unsigned r1u = (unsigned)(v1 - s0);
        if (r0u < (unsigned)RPB_) m |= 1u << r0u;
        if (r1u < (unsigned)RPB_) m |= 1u << r1u;
        m = __reduce_or_sync(0xFFFFFFFFu, m);
    }

#pragma unroll
    for (int i = 0; i < RPB_; ++i)
        if (!((m >> i) & 1u))
            __stcs(&dst[base + (size_t)i * D4_], v[i]);
}

// ---------------------------------------------------------------------------
extern "C" void kernel_launch(void* const* d_in, const int* in_sizes, int n_in,
                              void* d_out, int out_size) {
    const float* K_curr      = (const float*)d_in[0];
    const float* V_curr      = (const float*)d_in[1];
    const float* K_prev      = (const float*)d_in[2];
    const float* V_prev      = (const float*)d_in[3];
    const float* h           = (const float*)d_in[4];
    const float* momentum    = (const float*)d_in[5];
    const int*   active_idx  = (const int*)  d_in[6];
    const float* Wk          = (const float*)d_in[7];
    const float* bk          = (const float*)d_in[8];
    const float* Wv          = (const float*)d_in[9];
    const float* bv          = (const float*)d_in[10];
    const float* logit_eta   = (const float*)d_in[11];
    const float* alpha_logit = (const float*)d_in[12];

    float* out  = (float*)d_out;
    const size_t tensor_elems = (size_t)B_ * S_ * D_;
    float* outK = out;
    float* outV = out + tensor_elems;
    float* outM = out + 2 * tensor_elems;

    const bool forked = (g_side != nullptr && g_evFork != nullptr && g_evJoin != nullptr);
    cudaStream_t chain = forked ? g_side : (cudaStream_t)0;

    // ── Fork: probe chain + blend on side stream FIRST (small grids grab SMs
    //    immediately; the saturating copy back-fills around them) ──
    if (forked) {
        cudaEventRecord(g_evFork, 0);
        cudaStreamWaitEvent(g_side, g_evFork, 0);
    }

    k_probe_partial<<<dim3(NCHUNK_, B_), 256, 0, chain>>>((const float4*)h);
    k_qreduce<<<B_, 256, 0, chain>>>();
    k_logits<<<dim3(G_, B_, 2), 256, 0, chain>>>(K_curr, V_curr, active_idx);
    k_pred<<<dim3(PCHUNK_, B_, 2), PDIM_, 0, chain>>>(K_curr, V_curr, active_idx);
    // blend writes ONLY active rows -> no dependency on the bulk copy
    k_blend<<<dim3(G_, B_), 256, 0, chain>>>(K_curr, V_curr, K_prev, V_prev, active_idx,
                                             momentum, Wk, bk, Wv, bv,
                                             logit_eta, alpha_logit,
                                             outK, outV, outM);
    if (forked) cudaEventRecord(g_evJoin, g_side);

    // ── Main stream: bulk copy of all inactive rows (HBM-bound floor) ──
    k_copy<<<2 * B_ * S_ / RPB_, 256>>>((const float4*)K_curr, (const float4*)V_curr,
                                        active_idx, (float4*)outK, (float4*)outV);

    // ── Join back for capture correctness ──
    if (forked) cudaStreamWaitEvent((cudaStream_t)0, g_evJoin, 0);
}

// round 15
// speedup vs baseline: 1.0562x; 1.0003x over previous
#include <cuda_runtime.h>
#include <cuda_bf16.h>

// Problem constants
#define B_      8
#define S_      4096
#define D_      1024
#define D4_     (D_ / 4)
#define G_      64
#define HSEQ_   2048
#define NCHUNK_ 32
#define CROWS_  (HSEQ_ / NCHUNK_)   // 64 rows per chunk
#define PCHUNK_ 8                   // k_pred D-split
#define PDIM_   (D_ / PCHUNK_)      // 128 d per pred block
#define RPB_    16                  // rows per copy block (deep per-thread MLP)

// Scratch (allocation-free rule: __device__ globals)
__device__ float4 g_qpartial[B_ * NCHUNK_ * D4_];   // [b][chunk][d4]
__device__ float4 g_qprobe[B_ * D4_];               // [b][d4]
__device__ float  g_logits[2 * B_ * G_];            // [t][b][g]
__device__ float  g_sse[2 * B_ * PCHUNK_];          // [t][b][chunk] SSE partials

// Side stream + events for fork-join capture (created at static init).
static cudaStream_t g_side = nullptr;
static cudaEvent_t  g_evFork = nullptr, g_evJoin = nullptr;
namespace {
struct StreamInit {
    StreamInit() {
        cudaStreamCreateWithFlags(&g_side, cudaStreamNonBlocking);
        cudaEventCreateWithFlags(&g_evFork, cudaEventDisableTiming);
        cudaEventCreateWithFlags(&g_evJoin, cudaEventDisableTiming);
    }
};
static StreamInit g_streamInit;
}

// ---------------------------------------------------------------------------
// K1: partial column sums of h (float4, streaming). grid (NCHUNK_, B_), block 256
// ---------------------------------------------------------------------------
__global__ void k_probe_partial(const float4* __restrict__ h4) {
    const int v = threadIdx.x;
    const int c = blockIdx.x;
    const int b = blockIdx.y;
    const float4* p = h4 + ((size_t)b * HSEQ_ + (size_t)c * CROWS_) * D4_ + v;
    float4 acc = make_float4(0.f, 0.f, 0.f, 0.f);
#pragma unroll 16
    for (int s = 0; s < CROWS_; ++s) {
        const float4 x = __ldcs(&p[(size_t)s * D4_]);
        acc.x += x.x; acc.y += x.y; acc.z += x.z; acc.w += x.w;
    }
    g_qpartial[(b * NCHUNK_ + c) * D4_ + v] = acc;
}

// ---------------------------------------------------------------------------
// K2: reduce partials -> q_probe (mean). grid B_, block 256
// ---------------------------------------------------------------------------
__global__ void k_qreduce() {
    const int v = threadIdx.x;
    const int b = blockIdx.x;
    float4 acc = make_float4(0.f, 0.f, 0.f, 0.f);
#pragma unroll
    for (int c = 0; c < NCHUNK_; ++c) {
        const float4 x = g_qpartial[(b * NCHUNK_ + c) * D4_ + v];
        acc.x += x.x; acc.y += x.y; acc.z += x.z; acc.w += x.w;
    }
    const float inv = 1.0f / (float)HSEQ_;
    acc.x *= inv; acc.y *= inv; acc.z *= inv; acc.w *= inv;
    g_qprobe[b * D4_ + v] = acc;
}

// ---------------------------------------------------------------------------
// K3: logits. grid (G_, B_, 2), block 256 — one 1024-dot per block.
// ---------------------------------------------------------------------------
__global__ void k_logits(const float* __restrict__ K_curr,
                         const float* __restrict__ V_curr,
                         const int*   __restrict__ active_idx) {
    const int g = blockIdx.x;
    const int b = blockIdx.y;
    const int t = blockIdx.z;
    const int tid = threadIdx.x;
    const int wid = tid >> 5, lid = tid & 31;

    const float* X = (t == 0) ? K_curr : V_curr;
    const int row = __ldg(&active_idx[b * G_ + g]);
    const float4* xr = reinterpret_cast<const float4*>(X + ((size_t)b * S_ + row) * D_);

    const float4 q = g_qprobe[b * D4_ + tid];
    const float4 x = xr[tid];
    float acc = q.x * x.x + q.y * x.y + q.z * x.z + q.w * x.w;
#pragma unroll
    for (int off = 16; off > 0; off >>= 1)
        acc += __shfl_xor_sync(0xFFFFFFFFu, acc, off);

    __shared__ float sred[8];
    if (lid == 0) sred[wid] = acc;
    __syncthreads();
    if (tid == 0) {
        float tot = 0.f;
#pragma unroll
        for (int w = 0; w < 8; ++w) tot += sred[w];
        g_logits[(t * B_ + b) * G_ + g] = tot * (1.0f / 32.0f);  // * D^-0.5
    }
}

// ---------------------------------------------------------------------------
// K4: softmax + pred + SSE partials. grid (PCHUNK_, B_, 2), block 128
// ---------------------------------------------------------------------------
__global__ void k_pred(const float* __restrict__ K_curr,
                       const float* __restrict__ V_curr,
                       const int*   __restrict__ active_idx) {
    const int chunk = blockIdx.x;
    const int b = blockIdx.y;
    const int t = blockIdx.z;
    const int tid = threadIdx.x;
    const int wid = tid >> 5, lid = tid & 31;

    __shared__ float sattn[G_];
    __shared__ int   sidx[G_];
    __shared__ float sred[4];

    if (tid < G_) sidx[tid] = active_idx[b * G_ + tid];
    if (wid == 0) {
        float v0 = g_logits[(t * B_ + b) * G_ + lid];
        float v1 = g_logits[(t * B_ + b) * G_ + lid + 32];
        float m = fmaxf(v0, v1);
#pragma unroll
        for (int off = 16; off > 0; off >>= 1)
            m = fmaxf(m, __shfl_xor_sync(0xFFFFFFFFu, m, off));
        float e0 = __expf(v0 - m), e1 = __expf(v1 - m);
        float s = e0 + e1;
#pragma unroll
        for (int off = 16; off > 0; off >>= 1)
            s += __shfl_xor_sync(0xFFFFFFFFu, s, off);
        const float inv = 1.0f / s;
        sattn[lid]      = e0 * inv;
        sattn[lid + 32] = e1 * inv;
    }
    __syncthreads();

    const float* X  = (t == 0) ? K_curr : V_curr;
    const float* Xb = X + (size_t)b * S_ * D_;
    const int d = chunk * PDIM_ + tid;

    float pred = 0.f;
#pragma unroll 16
    for (int g = 0; g < G_; ++g)
        pred = fmaf(sattn[g], __ldg(&Xb[(size_t)sidx[g] * D_ + d]), pred);

    const float4 q4 = g_qprobe[b * D4_ + (d >> 2)];
    const float qv = (d & 3) == 0 ? q4.x : (d & 3) == 1 ? q4.y : (d & 3) == 2 ? q4.z : q4.w;
    const float diff = pred - qv;
    float acc = diff * diff;

#pragma unroll
    for (int off = 16; off > 0; off >>= 1)
        acc += __shfl_xor_sync(0xFFFFFFFFu, acc, off);
    if (lid == 0) sred[wid] = acc;
    __syncthreads();
    if (tid == 0) {
        float tot = sred[0] + sred[1] + sred[2] + sred[3];
        g_sse[(t * B_ + b) * PCHUNK_ + chunk] = tot;
    }
}

// ---------------------------------------------------------------------------
// K5: blend active rows + fused gates + momentum. grid (G_, B_), block 256.
//     Writes ONLY active output rows — runs concurrently with k_copy.
// ---------------------------------------------------------------------------
__device__ __forceinline__ float sigmoidf_(float x) { return 1.0f / (1.0f + __expf(-x)); }

__global__ void k_blend(const float* __restrict__ K_curr,
                        const float* __restrict__ V_curr,
                        const float* __restrict__ K_prev,
                        const float* __restrict__ V_prev,
                        const int*   __restrict__ active_idx,
                        const float* __restrict__ momentum,
                        const float* __restrict__ Wk,
                        const float* __restrict__ bk,
                        const float* __restrict__ Wv,
                        const float* __restrict__ bv,
                        const float* __restrict__ logit_eta,
                        const float* __restrict__ alpha_logit,
                        float* __restrict__ outK,
                        float* __restrict__ outV,
                        float* __restrict__ outM) {
    const int g = blockIdx.x;
    const int b = blockIdx.y;
    const int t = threadIdx.x;

    __shared__ float s_kg, s_vg;
    __shared__ int   s_row;
    if (t == 0) {
        float ks = 0.f, vs = 0.f;
#pragma unroll
        for (int c = 0; c < PCHUNK_; ++c) {
            ks += g_sse[(0 * B_ + b) * PCHUNK_ + c];
            vs += g_sse[(1 * B_ + b) * PCHUNK_ + c];
        }
        ks *= (1.0f / (float)D_);
        vs *= (1.0f / (float)D_);
        const float alpha = sigmoidf_(alpha_logit[0]);
        const float eta   = sigmoidf_(logit_eta[0]);
        const float combined = alpha * ks + (1.0f - alpha) * vs;
        const float mnew = eta * momentum[b] + (1.0f - eta) * combined;
        if (g == 0) outM[b] = mnew;
        s_kg = sigmoidf_(ks * Wk[g * 2 + 0] + mnew * Wk[g * 2 + 1] + bk[g]);
        s_vg = sigmoidf_(vs * Wv[g * 2 + 0] + mnew * Wv[g * 2 + 1] + bv[g]);
        s_row = active_idx[b * G_ + g];
    }
    __syncthreads();

    const float kg = s_kg, vg = s_vg;
    const size_t base = ((size_t)b * S_ + s_row) * D_;

    const float4 kc = reinterpret_cast<const float4*>(K_curr + base)[t];
    const float4 kp = reinterpret_cast<const float4*>(K_prev + base)[t];
    const float4 vc = reinterpret_cast<const float4*>(V_curr + base)[t];
    const float4 vp = reinterpret_cast<const float4*>(V_prev + base)[t];

    float4 ok, ov;
    ok.x = kg * kc.x + (1.0f - kg) * kp.x;
    ok.y = kg * kc.y + (1.0f - kg) * kp.y;
    ok.z = kg * kc.z + (1.0f - kg) * kp.z;
    ok.w = kg * kc.w + (1.0f - kg) * kp.w;
    ov.x = vg * vc.x + (1.0f - vg) * vp.x;
    ov.y = vg * vc.y + (1.0f - vg) * vp.y;
    ov.z = vg * vc.z + (1.0f - vg) * vp.z;
    ov.w = vg * vc.w + (1.0f - vg) * vp.w;

    reinterpret_cast<float4*>(outK + base)[t] = ok;
    reinterpret_cast<float4*>(outV + base)[t] = ov;
}

// ---------------------------------------------------------------------------
// K6: bulk copy of all rows, skipping active rows (blend writes those).
//     grid: 2 * B_*S_ / RPB_ blocks (K/V interleaved), block 256.
//     16 front-batched float4 loads per thread (256B in flight), per-warp
//     16-bit ballot mask, no smem, no barrier.
// ---------------------------------------------------------------------------
__global__ void k_copy(const float4* __restrict__ K_curr,
                       const float4* __restrict__ V_curr,
                       const int*    __restrict__ active_idx,
                       float4* __restrict__ outK,
                       float4* __restrict__ outV) {
    const int blk    = blockIdx.x;
    const int tensor = blk & 1;                   // interleave K/V
    const int rblk   = blk >> 1;
    const int r0     = rblk * RPB_;               // row within tensor (0..32767)
    const int b      = r0 >> 12;                  // S_ = 4096
    const int s0     = r0 & (S_ - 1);
    const int tid    = threadIdx.x;
    const int lid    = tid & 31;

    const float4* src = (tensor == 0) ? K_curr : V_curr;
    float4*       dst = (tensor == 0) ? outK   : outV;
    const size_t base = ((size_t)b * S_ + s0) * D4_ + tid;

    // Front-batch all loads (active rows loaded but not stored)
    float4 v[RPB_];
#pragma unroll
    for (int i = 0; i < RPB_; ++i)
        v[i] = __ldcs(&src[base + (size_t)i * D4_]);

    // Per-warp active-row mask (broadcast L1-hit loads, no barrier)
    unsigned m = 0;
    {
        const int v0 = __ldg(&active_idx[b * G_ + lid]);
        const int v1 = __ldg(&active_idx[b * G_ + lid + 32]);
        const unsigned r0u = (unsigned)(v0 - s0);
        const unsigned r1u = (unsigned)(v1 - s0);
        if (r0u < (unsigned)RPB_) m |= 1u << r0u;
        if (r1u < (unsigned)RPB_) m |= 1u << r1u;
        m = __reduce_or_sync(0xFFFFFFFFu, m);
    }

#pragma unroll
    for (int i = 0; i < RPB_; ++i)
        if (!((m >> i) & 1u))
            __stcs(&dst[base + (size_t)i * D4_], v[i]);
}

// ---------------------------------------------------------------------------
extern "C" void kernel_launch(void* const* d_in, const int* in_sizes, int n_in,
                              void* d_out, int out_size) {
    const float* K_curr      = (const float*)d_in[0];
    const float* V_curr      = (const float*)d_in[1];
    const float* K_prev      = (const float*)d_in[2];
    const float* V_prev      = (const float*)d_in[3];
    const float* h           = (const float*)d_in[4];
    const float* momentum    = (const float*)d_in[5];
    const int*   active_idx  = (const int*)  d_in[6];
    const float* Wk          = (const float*)d_in[7];
    const float* bk          = (const float*)d_in[8];
    const float* Wv          = (const float*)d_in[9];
    const float* bv          = (const float*)d_in[10];
    const float* logit_eta   = (const float*)d_in[11];
    const float* alpha_logit = (const float*)d_in[12];

    float* out  = (float*)d_out;
    const size_t tensor_elems = (size_t)B_ * S_ * D_;
    float* outK = out;
    float* outV = out + tensor_elems;
    float* outM = out + 2 * tensor_elems;

    const bool forked = (g_side != nullptr && g_evFork != nullptr && g_evJoin != nullptr);
    cudaStream_t chain = forked ? g_side : (cudaStream_t)0;

    // ── Fork: probe chain + blend on side stream FIRST (small grids grab SMs
    //    immediately; the saturating copy back-fills around them) ──
    if (forked) {
        cudaEventRecord(g_evFork, 0);
        cudaStreamWaitEvent(g_side, g_evFork, 0);
    }

    k_probe_partial<<<dim3(NCHUNK_, B_), 256, 0, chain>>>((const float4*)h);
    k_qreduce<<<B_, 256, 0, chain>>>();
    k_logits<<<dim3(G_, B_, 2), 256, 0, chain>>>(K_curr, V_curr, active_idx);
    k_pred<<<dim3(PCHUNK_, B_, 2), PDIM_, 0, chain>>>(K_curr, V_curr, active_idx);
    // blend writes ONLY active rows -> no dependency on the bulk copy
    k_blend<<<dim3(G_, B_), 256, 0, chain>>>(K_curr, V_curr, K_prev, V_prev, active_idx,
                                             momentum, Wk, bk, Wv, bv,
                                             logit_eta, alpha_logit,
                                             outK, outV, outM);
    if (forked) cudaEventRecord(g_evJoin, g_side);

    // ── Main stream: bulk copy of all inactive rows (HBM-bound floor) ──
    k_copy<<<2 * B_ * S_ / RPB_, 256>>>((const float4*)K_curr, (const float4*)V_curr,
                                        active_idx, (float4*)outK, (float4*)outV);

    // ── Join back for capture correctness ──
    if (forked) cudaStreamWaitEvent((cudaStream_t)0, g_evJoin, 0);
}